// round 14
// baseline (speedup 1.0000x reference)
#include <cuda_runtime.h>
#include <cstdio>

// ---------------- scratch (device globals; no runtime allocation) ----------------
__device__ float g_h1[32*128*64*64];   // enc conv1 out (relu)
__device__ float g_p [2048*128];       // pooled encoder features [m][c]
__device__ float g_z [2048*64];        // z_e vectors [m][d]
__device__ int   g_idx[2048];          // argmin code per cell
__device__ float g_y0[2048*128];       // relu(dproj) [m][c]
__device__ float g_T [2048*1152];      // tap GEMM out [m][tap*128+o]
__device__ float g_loss[2048];         // per-cell loss partials

#define N_XHAT 1572864   // 32*3*128*128
#define N_IDX  2048      // 32*8*8
#define N_ZE   131072    // 32*64*8*8
#define N_FULL (N_XHAT + N_IDX + 1 + N_ZE)   // 1,705,985 == out_size (ground truth)

// ---- packed fp32x2 helpers (Blackwell FFMA2; PTX-only) ----
typedef unsigned long long ull;
__device__ __forceinline__ ull pack2(float lo, float hi) {
    ull r;
    asm("mov.b64 %0, {%1, %2};" : "=l"(r) : "f"(lo), "f"(hi));
    return r;
}
__device__ __forceinline__ void unpack2(ull v, float& lo, float& hi) {
    asm("mov.b64 {%0, %1}, %2;" : "=f"(lo), "=f"(hi) : "l"(v));
}
__device__ __forceinline__ ull ffma2(ull a, ull b, ull c) {
    ull d;
    asm("fma.rn.f32x2 %0, %1, %2, %3;" : "=l"(d) : "l"(a), "l"(b), "l"(c));
    return d;
}

// ============ K1: enc conv1  3->128, 3x3, stride2 pad1, relu ============
__global__ __launch_bounds__(256) void k1_conv1(const float* __restrict__ x,
        const float* __restrict__ w, const float* __restrict__ bias) {
    __shared__ float xt[3][33][33];
    __shared__ float ws[3456];
    int b = blockIdx.z;
    int oh0 = blockIdx.y * 16, ow0 = blockIdx.x * 16;
    int tid = threadIdx.x;
    for (int idx = tid; idx < 3*33*33; idx += 256) {
        int c = idx / 1089, rr = idx % 1089, yy = rr / 33, xx = rr % 33;
        int iy = 2*oh0 - 1 + yy, ix = 2*ow0 - 1 + xx;
        float v = 0.f;
        if (iy >= 0 && iy < 128 && ix >= 0 && ix < 128)
            v = x[((b*3 + c)*128 + iy)*128 + ix];
        xt[c][yy][xx] = v;
    }
    for (int idx = tid; idx < 3456; idx += 256) ws[idx] = w[idx];
    __syncthreads();
    int r = tid >> 4, col = tid & 15;
    float xr[27];
    #pragma unroll
    for (int c = 0; c < 3; c++)
      #pragma unroll
      for (int ky = 0; ky < 3; ky++)
        #pragma unroll
        for (int kx = 0; kx < 3; kx++)
            xr[c*9 + ky*3 + kx] = xt[c][2*r + ky][2*col + kx];
    int oh = oh0 + r, ow = ow0 + col;
    for (int o = 0; o < 128; o++) {
        float acc = bias[o];
        #pragma unroll
        for (int j = 0; j < 27; j++) acc += ws[o*27 + j] * xr[j];
        g_h1[((b*128 + o)*64 + oh)*64 + ow] = fmaxf(acc, 0.f);
    }
}

// ============ K2: enc conv2 (packed f32x2) + relu + fused 4x4 pool -> g_p =======
__global__ __launch_bounds__(256) void k2_conv2(const float* __restrict__ w,
        const float* __restrict__ bias) {
    __shared__ float xs[8][9][66];
    __shared__ float ws[64][72];
    int b = blockIdx.z;
    int oh0 = blockIdx.y * 4;
    int o0 = blockIdx.x * 64;
    int tid = threadIdx.x;
    int tx = tid & 31, ty = tid >> 5;
    // acc2[i][p] packs output rows (2p, 2p+1) for out-channel o = ty + 8*i
    ull acc2[8][2];
    #pragma unroll
    for (int i = 0; i < 8; i++)
      #pragma unroll
      for (int p = 0; p < 2; p++) acc2[i][p] = 0ull;

    for (int cc = 0; cc < 16; cc++) {
        int c0 = cc * 8;
        __syncthreads();
        for (int idx = tid; idx < 8*9*65; idx += 256) {
            int c = idx / 585, rr = idx % 585, yy = rr / 65, xx = rr % 65;
            int iy = 2*oh0 - 1 + yy, ix = xx - 1;
            float v = 0.f;
            if (iy >= 0 && iy < 64 && ix >= 0 && ix < 64)
                v = g_h1[((b*128 + c0 + c)*64 + iy)*64 + ix];
            xs[c][yy][xx] = v;
        }
        for (int idx = tid; idx < 64*72; idx += 256) {
            int o = idx / 72, r = idx % 72;  // r = c*9 + tap
            ws[o][r] = w[((o0 + o)*128 + c0 + r/9)*9 + (r % 9)];
        }
        __syncthreads();
        #pragma unroll 1
        for (int c = 0; c < 8; c++) {
            float xv[9][3];
            #pragma unroll
            for (int yy = 0; yy < 9; yy++)
              #pragma unroll
              for (int kx = 0; kx < 3; kx++)
                xv[yy][kx] = xs[c][yy][2*tx + kx];
            // packed multiplicands: rows (ky, ky+2) and (ky+4, ky+6)
            ull xp[2][3][3];
            #pragma unroll
            for (int ky = 0; ky < 3; ky++)
              #pragma unroll
              for (int kx = 0; kx < 3; kx++) {
                xp[0][ky][kx] = pack2(xv[ky][kx],     xv[ky + 2][kx]);
                xp[1][ky][kx] = pack2(xv[ky + 4][kx], xv[ky + 6][kx]);
              }
            #pragma unroll
            for (int i = 0; i < 8; i++) {
                int o = ty + 8*i;
                #pragma unroll
                for (int t9 = 0; t9 < 9; t9++) {
                    float wv = ws[o][c*9 + t9];
                    ull w2p = pack2(wv, wv);
                    int ky = t9 / 3, kx = t9 % 3;
                    acc2[i][0] = ffma2(w2p, xp[0][ky][kx], acc2[i][0]);
                    acc2[i][1] = ffma2(w2p, xp[1][ky][kx], acc2[i][1]);
                }
            }
        }
    }
    // fused relu + 4x4 pool
    #pragma unroll
    for (int i = 0; i < 8; i++) {
        int o = o0 + ty + 8*i;
        float bv = bias[o];
        float r0, r1, r2, r3;
        unpack2(acc2[i][0], r0, r1);
        unpack2(acc2[i][1], r2, r3);
        float rs = fmaxf(r0 + bv, 0.f) + fmaxf(r1 + bv, 0.f)
                 + fmaxf(r2 + bv, 0.f) + fmaxf(r3 + bv, 0.f);
        rs += __shfl_xor_sync(0xffffffffu, rs, 1);
        rs += __shfl_xor_sync(0xffffffffu, rs, 2);
        if ((tx & 3) == 0) {
            int cell = blockIdx.y * 8 + (tx >> 2);
            g_p[(b*64 + cell)*128 + o] = rs * 0.0625f;
        }
    }
}

// ============ K3z: proj 1x1 128->64 as smem-staged GEMM (16 cells/block) ========
__global__ __launch_bounds__(256) void k3z_proj(
    const float* __restrict__ pw, const float* __restrict__ pb,
    float* __restrict__ out) {
    __shared__ float pws[64][129];
    __shared__ float ps[16][129];
    int m0 = blockIdx.x * 16;
    int tid = threadIdx.x;
    for (int i = tid; i < 64*128; i += 256) pws[i >> 7][i & 127] = pw[i];
    for (int i = tid; i < 16*128; i += 256) ps[i >> 7][i & 127] = g_p[m0*128 + i];
    __syncthreads();
    #pragma unroll
    for (int q = 0; q < 4; q++) {
        int jj = tid + q*256;
        int c = jj >> 6, d = jj & 63;
        float a = pb[d];
        #pragma unroll 8
        for (int k = 0; k < 128; k++) a += pws[d][k] * ps[c][k];
        int m = m0 + c;
        g_z[m*64 + d] = a;
        int b = m >> 6, cell = m & 63;
        out[(long long)N_XHAT + N_IDX + 1 + (long long)b*4096 + d*64 + cell] = a;
    }
}

// ============ K3b: VQ argmin as tiled smem GEMM (16 cells/block) ============
__global__ __launch_bounds__(256) void k3b_vq(const float* __restrict__ cb,
                                              float* __restrict__ out) {
    __shared__ float zb[16][65];
    __shared__ float cbs[128][65];
    __shared__ float z2s[16];
    __shared__ float bd[256];
    __shared__ int   bi[256];
    int m0 = blockIdx.x * 16;
    int tid = threadIdx.x;
    for (int i = tid; i < 16*64; i += 256) zb[i >> 6][i & 63] = g_z[m0*64 + i];
    __syncthreads();
    if (tid < 16) {
        float s = 0.f;
        #pragma unroll 8
        for (int d = 0; d < 64; d++) { float z = zb[tid][d]; s += z*z; }
        z2s[tid] = s;
    }
    int c = tid & 15, kg = tid >> 4;
    float best = 3.4e38f; int bidx = 0;
    for (int ch = 0; ch < 4; ch++) {
        __syncthreads();
        for (int i = tid; i < 128*64; i += 256)
            cbs[i >> 6][i & 63] = cb[ch*128*64 + i];
        __syncthreads();
        float dot[8], cc2[8];
        #pragma unroll
        for (int j = 0; j < 8; j++) { dot[j] = 0.f; cc2[j] = 0.f; }
        #pragma unroll 4
        for (int d = 0; d < 64; d++) {
            float zv = zb[c][d];
            #pragma unroll
            for (int j = 0; j < 8; j++) {
                float cv = cbs[kg + 16*j][d];
                dot[j] += zv * cv;
                cc2[j] += cv * cv;
            }
        }
        float z2 = z2s[c];
        #pragma unroll
        for (int j = 0; j < 8; j++) {
            int k = ch*128 + kg + 16*j;
            float dist = z2 + cc2[j] - 2.f*dot[j];
            if (dist < best || (dist == best && k < bidx)) { best = dist; bidx = k; }
        }
    }
    bd[tid] = best; bi[tid] = bidx;
    __syncthreads();
    for (int s = 128; s >= 16; s >>= 1) {
        if (tid < s) {
            float d2 = bd[tid + s]; int i2 = bi[tid + s];
            if (d2 < bd[tid] || (d2 == bd[tid] && i2 < bi[tid])) { bd[tid] = d2; bi[tid] = i2; }
        }
        __syncthreads();
    }
    if (tid < 16) {
        g_idx[m0 + tid] = bi[tid];
        out[N_XHAT + m0 + tid] = (float)bi[tid];
    }
}

// ============ K4: zq gather + loss partial + dproj 1x1 + relu (smem-staged w) ====
__global__ __launch_bounds__(128) void k4_dproj(const float* __restrict__ w,
        const float* __restrict__ bias, const float* __restrict__ cb) {
    __shared__ float ws[128][65];
    __shared__ float zq[64];
    __shared__ float red[64];
    int m = blockIdx.x, tid = threadIdx.x;
    for (int i = tid; i < 128*64; i += 128) ws[i >> 6][i & 63] = w[i];
    int qi = g_idx[m];
    if (tid < 64) {
        float q = cb[qi*64 + tid];
        zq[tid] = q;
        float df = q - g_z[m*64 + tid];
        red[tid] = df*df;
    }
    __syncthreads();
    for (int s = 32; s > 0; s >>= 1) {
        if (tid < s) red[tid] += red[tid + s];
        __syncthreads();
    }
    if (tid == 0) g_loss[m] = red[0];
    float a = bias[tid];
    #pragma unroll 8
    for (int d = 0; d < 64; d++) a += ws[tid][d] * zq[d];
    g_y0[m*128 + tid] = fmaxf(a, 0.f);
}

// ============ K5: tap GEMM  T[m][tap*128+o] = sum_c w1[o][c][tap] * y0[m][c] =====
__global__ __launch_bounds__(256) void k5_gemm(const float* __restrict__ w1) {
    __shared__ float Ys[64][33];
    __shared__ float Ws[64][33];
    int m0 = blockIdx.x * 64, n0 = blockIdx.y * 64;
    int tid = threadIdx.x;
    int tn4 = (tid & 15) * 4, tm4 = (tid >> 4) * 4;
    float acc[4][4] = {};
    for (int kc = 0; kc < 4; kc++) {
        int k0 = kc * 32;
        __syncthreads();
        for (int idx = tid; idx < 2048; idx += 256) {
            int row = idx >> 5, col = idx & 31;
            Ys[row][col] = g_y0[(m0 + row)*128 + k0 + col];
            int n = n0 + row;
            int o = n & 127, tap = n >> 7;
            Ws[row][col] = w1[(o*128 + k0 + col)*9 + tap];
        }
        __syncthreads();
        #pragma unroll
        for (int kk = 0; kk < 32; kk++) {
            float a[4], bb[4];
            #pragma unroll
            for (int i = 0; i < 4; i++) a[i] = Ys[tm4+i][kk];
            #pragma unroll
            for (int j = 0; j < 4; j++) bb[j] = Ws[tn4+j][kk];
            #pragma unroll
            for (int i = 0; i < 4; i++)
              #pragma unroll
              for (int j = 0; j < 4; j++)
                acc[i][j] += a[i]*bb[j];
        }
    }
    #pragma unroll
    for (int i = 0; i < 4; i++)
      #pragma unroll
      for (int j = 0; j < 4; j++)
        g_T[(m0 + tm4 + i)*1152 + n0 + tn4 + j] = acc[i][j];
}

// ============ K6: gather + 9-type recombination + relu + dconv2 + store x_hat ===
__global__ __launch_bounds__(128) void k6_dec(const float* __restrict__ b1,
        const float* __restrict__ w2, const float* __restrict__ b2,
        float* __restrict__ out) {
    __shared__ float Ts[25][128];
    __shared__ float vss[9][129];
    __shared__ float xv[27];
    int m = blockIdx.x;
    int b = m >> 6, cell = m & 63, gh = cell >> 3, gw = cell & 7;
    int tid = threadIdx.x;
    const int av[5] = {-1, 0, 0, 0, 1};
    const int dv[5] = {-1,-1, 0, 1, 1};
    #pragma unroll
    for (int p = 0; p < 25; p++) {
        const int iv = p / 5, ih = p % 5;
        int gr = gh + av[iv], gc = gw + av[ih];
        float v = 0.f;
        if (gr >= 0 && gr < 8 && gc >= 0 && gc < 8) {
            long long idx = (long long)(b*64 + gr*8 + gc)*1152
                          + (long long)((dv[iv]+1)*3 + (dv[ih]+1))*128 + tid;
            v = g_T[idx];
        }
        Ts[p][tid] = v;
    }
    __syncthreads();
    float bv = b1[tid];
    const int ivt[3][3] = {{0,2,3},{1,2,3},{1,2,4}};   // [row_type][dy+1] -> plane
    #pragma unroll
    for (int ry = 0; ry < 3; ry++)
      #pragma unroll
      for (int rx = 0; rx < 3; rx++) {
        float s = bv;
        #pragma unroll
        for (int dy = 0; dy < 3; dy++)
          #pragma unroll
          for (int dx = 0; dx < 3; dx++)
            s += Ts[ivt[ry][dy]*5 + ivt[rx][dx]][tid];
        vss[ry*3 + rx][tid] = fmaxf(s, 0.f);
      }
    __syncthreads();
    if (tid < 27) {
        int t = tid / 3, c3 = tid % 3;
        float s = b2[c3];
        #pragma unroll 8
        for (int o = 0; o < 128; o++) s += w2[c3*128 + o] * vss[t][o];
        xv[tid] = s;
    }
    __syncthreads();
    for (int i = tid; i < 768; i += 128) {
        int c3 = i >> 8, rem = i & 255, r = rem >> 4, col = rem & 15;
        int ry = (r == 0) ? 0 : (r == 15) ? 2 : 1;
        int rx = (col == 0) ? 0 : (col == 15) ? 2 : 1;
        long long pos = (long long)(b*3 + c3)*16384 + (gh*16 + r)*128 + gw*16 + col;
        out[pos] = xv[(ry*3 + rx)*3 + c3];
    }
}

// ============ K7: deterministic loss reduction ============
__global__ __launch_bounds__(256) void k7_loss(float* __restrict__ out) {
    __shared__ float red[256];
    int tid = threadIdx.x;
    float s = 0.f;
    for (int j = tid; j < 2048; j += 256) s += g_loss[j];
    red[tid] = s;
    __syncthreads();
    for (int st = 128; st > 0; st >>= 1) {
        if (tid < st) red[tid] += red[tid + st];
        __syncthreads();
    }
    if (tid == 0) out[N_XHAT + N_IDX] = 1.25f * red[0] / 131072.0f;
}

// ============ fallback ============
__global__ void k_probe(float* out) { if (threadIdx.x == 0) out[0] = 0.f; }

// ============ launch ============
extern "C" void kernel_launch(void* const* d_in, const int* in_sizes, int n_in,
                              void* d_out, int out_size) {
    cudaStreamCaptureStatus cst = cudaStreamCaptureStatusNone;
    cudaStreamIsCapturing(0, &cst);
    const bool dbg = (cst == cudaStreamCaptureStatusNone);

#define HX_CK(NAME) do { if (dbg) { \
        cudaError_t e_ = cudaStreamSynchronize(0); \
        cudaError_t l_ = cudaGetLastError(); \
        if (e_ != cudaSuccess || l_ != cudaSuccess) { \
            fprintf(stderr, "HXDBG after %s: sync=%s last=%s\n", NAME, \
                    cudaGetErrorString(e_), cudaGetErrorString(l_)); \
            fflush(stderr); return; } } } while (0)

    static const int sig_ins[14] = {1572864, 3456, 128, 147456, 128, 8192, 64,
                                    32768, 8192, 128, 147456, 128, 384, 3};
    bool is_ins = (n_in >= 14);
    for (int i = 0; i < 14 && is_ins; i++)
        if (in_sizes[i] != sig_ins[i]) is_ins = false;
    if (!is_ins || out_size < N_FULL) {
        k_probe<<<1, 32>>>((float*)d_out);
        HX_CK("probe");
        return;
    }

    const float* x   = (const float*)d_in[0];
    const float* ew1 = (const float*)d_in[1];
    const float* eb1 = (const float*)d_in[2];
    const float* ew2 = (const float*)d_in[3];
    const float* eb2 = (const float*)d_in[4];
    const float* pw  = (const float*)d_in[5];
    const float* pb  = (const float*)d_in[6];
    const float* cb  = (const float*)d_in[7];
    const float* dpw = (const float*)d_in[8];
    const float* dpb = (const float*)d_in[9];
    const float* dw1 = (const float*)d_in[10];
    const float* db1 = (const float*)d_in[11];
    const float* dw2 = (const float*)d_in[12];
    const float* db2 = (const float*)d_in[13];
    float* out = (float*)d_out;

    k1_conv1<<<dim3(4, 4, 32), 256>>>(x, ew1, eb1);
    HX_CK("k1_conv1");
    k2_conv2<<<dim3(2, 8, 32), 256>>>(ew2, eb2);
    HX_CK("k2_conv2");
    k3z_proj<<<128, 256>>>(pw, pb, out);
    HX_CK("k3z_proj");
    k3b_vq<<<128, 256>>>(cb, out);
    HX_CK("k3b_vq");
    k4_dproj<<<2048, 128>>>(dpw, dpb, cb);
    HX_CK("k4_dproj");
    k5_gemm<<<dim3(32, 18), 256>>>(dw1);
    HX_CK("k5_gemm");
    k6_dec<<<2048, 128>>>(db1, dw2, db2, out);
    HX_CK("k6_dec");
    k7_loss<<<1, 256>>>(out);
    HX_CK("k7_loss");
#undef HX_CK
}

// round 15
// speedup vs baseline: 1.1007x; 1.1007x over previous
#include <cuda_runtime.h>
#include <cstdio>

// ---------------- scratch (device globals; no runtime allocation) ----------------
__device__ float g_h1[32*128*64*64];   // enc conv1 out (relu)
__device__ float g_p [2048*128];       // pooled encoder features [m][c]
__device__ float g_y0[2048*128];       // relu(dproj) [m][c]
__device__ float g_T [2048*1152];      // tap GEMM out [m][tap*128+o]
__device__ float g_loss[2048];         // per-cell loss partials

#define N_XHAT 1572864   // 32*3*128*128
#define N_IDX  2048      // 32*8*8
#define N_ZE   131072    // 32*64*8*8
#define N_FULL (N_XHAT + N_IDX + 1 + N_ZE)   // 1,705,985 == out_size (ground truth)

// ============ K1: enc conv1  3->128, 3x3, stride2 pad1, relu ============
__global__ __launch_bounds__(256) void k1_conv1(const float* __restrict__ x,
        const float* __restrict__ w, const float* __restrict__ bias) {
    __shared__ float xt[3][33][33];
    __shared__ float ws[3456];
    int b = blockIdx.z;
    int oh0 = blockIdx.y * 16, ow0 = blockIdx.x * 16;
    int tid = threadIdx.x;
    for (int idx = tid; idx < 3*33*33; idx += 256) {
        int c = idx / 1089, rr = idx % 1089, yy = rr / 33, xx = rr % 33;
        int iy = 2*oh0 - 1 + yy, ix = 2*ow0 - 1 + xx;
        float v = 0.f;
        if (iy >= 0 && iy < 128 && ix >= 0 && ix < 128)
            v = x[((b*3 + c)*128 + iy)*128 + ix];
        xt[c][yy][xx] = v;
    }
    for (int idx = tid; idx < 3456; idx += 256) ws[idx] = w[idx];
    __syncthreads();
    int r = tid >> 4, col = tid & 15;
    float xr[27];
    #pragma unroll
    for (int c = 0; c < 3; c++)
      #pragma unroll
      for (int ky = 0; ky < 3; ky++)
        #pragma unroll
        for (int kx = 0; kx < 3; kx++)
            xr[c*9 + ky*3 + kx] = xt[c][2*r + ky][2*col + kx];
    int oh = oh0 + r, ow = ow0 + col;
    for (int o = 0; o < 128; o++) {
        float acc = bias[o];
        #pragma unroll
        for (int j = 0; j < 27; j++) acc += ws[o*27 + j] * xr[j];
        g_h1[((b*128 + o)*64 + oh)*64 + ow] = fmaxf(acc, 0.f);
    }
}

// ============ K2: enc conv2 + relu + fused 4x4 pool -> g_p (R13 scalar form) =====
__global__ __launch_bounds__(256) void k2_conv2(const float* __restrict__ w,
        const float* __restrict__ bias) {
    __shared__ float xs[8][9][66];
    __shared__ float ws[64][72];
    int b = blockIdx.z;
    int oh0 = blockIdx.y * 4;
    int o0 = blockIdx.x * 64;
    int tid = threadIdx.x;
    int tx = tid & 31, ty = tid >> 5;
    float acc[8][4];
    #pragma unroll
    for (int i = 0; i < 8; i++)
      #pragma unroll
      for (int r = 0; r < 4; r++) acc[i][r] = 0.f;

    for (int cc = 0; cc < 16; cc++) {
        int c0 = cc * 8;
        __syncthreads();
        for (int idx = tid; idx < 8*9*65; idx += 256) {
            int c = idx / 585, rr = idx % 585, yy = rr / 65, xx = rr % 65;
            int iy = 2*oh0 - 1 + yy, ix = xx - 1;
            float v = 0.f;
            if (iy >= 0 && iy < 64 && ix >= 0 && ix < 64)
                v = g_h1[((b*128 + c0 + c)*64 + iy)*64 + ix];
            xs[c][yy][xx] = v;
        }
        for (int idx = tid; idx < 64*72; idx += 256) {
            int o = idx / 72, r = idx % 72;  // r = c*9 + tap
            ws[o][r] = w[((o0 + o)*128 + c0 + r/9)*9 + (r % 9)];
        }
        __syncthreads();
        #pragma unroll 1
        for (int c = 0; c < 8; c++) {
            float xv[9][3];
            #pragma unroll
            for (int yy = 0; yy < 9; yy++)
              #pragma unroll
              for (int kx = 0; kx < 3; kx++)
                xv[yy][kx] = xs[c][yy][2*tx + kx];
            #pragma unroll
            for (int i = 0; i < 8; i++) {
                int o = ty + 8*i;
                float wr[9];
                #pragma unroll
                for (int t9 = 0; t9 < 9; t9++) wr[t9] = ws[o][c*9 + t9];
                #pragma unroll
                for (int r = 0; r < 4; r++) {
                    float s = acc[i][r];
                    #pragma unroll
                    for (int ky = 0; ky < 3; ky++)
                      #pragma unroll
                      for (int kx = 0; kx < 3; kx++)
                        s += wr[ky*3 + kx] * xv[2*r + ky][kx];
                    acc[i][r] = s;
                }
            }
        }
    }
    #pragma unroll
    for (int i = 0; i < 8; i++) {
        int o = o0 + ty + 8*i;
        float bv = bias[o];
        float rs = 0.f;
        #pragma unroll
        for (int r = 0; r < 4; r++) rs += fmaxf(acc[i][r] + bv, 0.f);
        rs += __shfl_xor_sync(0xffffffffu, rs, 1);
        rs += __shfl_xor_sync(0xffffffffu, rs, 2);
        if ((tx & 3) == 0) {
            int cell = blockIdx.y * 8 + (tx >> 2);
            g_p[(b*64 + cell)*128 + o] = rs * 0.0625f;
        }
    }
}

// ============ K3: FUSED proj + VQ + zq/loss + dproj (16 cells/block, 1 wave) ====
// Static smem 45.5 KB: zb/z2s/qis persistent + phase-overlaid scratch.
__global__ __launch_bounds__(256) void k3_fused(
    const float* __restrict__ pw, const float* __restrict__ pb,
    const float* __restrict__ cb,
    const float* __restrict__ dpw, const float* __restrict__ dpb,
    float* __restrict__ out) {
    __shared__ float zb[16][65];
    __shared__ float z2s[16];
    __shared__ int   qis[16];
    __shared__ char  scr[41280];
    float (*pws)[129] = reinterpret_cast<float(*)[129]>(scr);            // phase A: 33024 B
    float (*ps)[129]  = reinterpret_cast<float(*)[129]>(scr + 33024);    // phase A: 8256 B
    float (*cbs)[65]  = reinterpret_cast<float(*)[65]>(scr);             // phase B: 33280 B
    float* bd         = reinterpret_cast<float*>(scr + 33280);           // phase B: 1024 B
    int*   bi         = reinterpret_cast<int*>(scr + 34304);             // phase B: 1024 B
    float (*dws)[65]  = reinterpret_cast<float(*)[65]>(scr);             // phase C: 33280 B
    float (*zqs)[64]  = reinterpret_cast<float(*)[64]>(scr + 33280);     // phase C: 4096 B

    int m0 = blockIdx.x * 16;
    int tid = threadIdx.x;

    // ---- phase A: stage pw + pooled features, compute z (same FP order as k3z) --
    for (int i = tid; i < 64*128; i += 256) pws[i >> 7][i & 127] = pw[i];
    for (int i = tid; i < 16*128; i += 256) ps[i >> 7][i & 127] = g_p[m0*128 + i];
    __syncthreads();
    #pragma unroll
    for (int q = 0; q < 4; q++) {
        int jj = tid + q*256;
        int c = jj >> 6, d = jj & 63;
        float a = pb[d];
        #pragma unroll 8
        for (int k = 0; k < 128; k++) a += pws[d][k] * ps[c][k];
        zb[c][d] = a;
        int m = m0 + c, b = m >> 6, cell = m & 63;
        out[(long long)N_XHAT + N_IDX + 1 + (long long)b*4096 + d*64 + cell] = a;
    }
    __syncthreads();
    if (tid < 16) {
        float s = 0.f;
        #pragma unroll 8
        for (int d = 0; d < 64; d++) { float z = zb[tid][d]; s += z*z; }
        z2s[tid] = s;
    }

    // ---- phase B: VQ argmin over codebook chunks ----
    int c = tid & 15, kg = tid >> 4;
    float best = 3.4e38f; int bidx = 0;
    for (int ch = 0; ch < 4; ch++) {
        __syncthreads();
        for (int i = tid; i < 128*64; i += 256)
            cbs[i >> 6][i & 63] = cb[ch*128*64 + i];
        __syncthreads();
        float dot[8], cc2[8];
        #pragma unroll
        for (int j = 0; j < 8; j++) { dot[j] = 0.f; cc2[j] = 0.f; }
        #pragma unroll 4
        for (int d = 0; d < 64; d++) {
            float zv = zb[c][d];
            #pragma unroll
            for (int j = 0; j < 8; j++) {
                float cv = cbs[kg + 16*j][d];
                dot[j] += zv * cv;
                cc2[j] += cv * cv;
            }
        }
        float z2 = z2s[c];
        #pragma unroll
        for (int j = 0; j < 8; j++) {
            int k = ch*128 + kg + 16*j;
            float dist = z2 + cc2[j] - 2.f*dot[j];
            if (dist < best || (dist == best && k < bidx)) { best = dist; bidx = k; }
        }
    }
    __syncthreads();          // cbs reads done before bd/bi writes alias checks
    bd[tid] = best; bi[tid] = bidx;
    __syncthreads();
    for (int s = 128; s >= 16; s >>= 1) {
        if (tid < s) {
            float d2 = bd[tid + s]; int i2 = bi[tid + s];
            if (d2 < bd[tid] || (d2 == bd[tid] && i2 < bi[tid])) { bd[tid] = d2; bi[tid] = i2; }
        }
        __syncthreads();
    }
    if (tid < 16) {
        qis[tid] = bi[tid];
        out[N_XHAT + m0 + tid] = (float)bi[tid];
    }
    __syncthreads();

    // ---- phase C: zq gather + loss + dproj (same FP order as k4) ----
    for (int i = tid; i < 128*64; i += 256) dws[i >> 6][i & 63] = dpw[i];
    for (int i = tid; i < 16*64; i += 256) {
        int cc2i = i >> 6, d = i & 63;
        zqs[cc2i][d] = cb[qis[cc2i]*64 + d];
    }
    __syncthreads();
    if (tid < 16) {
        float s = 0.f;
        #pragma unroll 8
        for (int d = 0; d < 64; d++) {
            float df = zqs[tid][d] - zb[tid][d];
            s += df*df;
        }
        g_loss[m0 + tid] = s;
    }
    #pragma unroll
    for (int q = 0; q < 8; q++) {
        int j = tid + q*256;
        int cc3 = j >> 7, o = j & 127;
        float a = dpb[o];
        #pragma unroll 8
        for (int d = 0; d < 64; d++) a += dws[o][d] * zqs[cc3][d];
        g_y0[(m0 + cc3)*128 + o] = fmaxf(a, 0.f);
    }
}

// ============ K5: tap GEMM  T[m][tap*128+o] = sum_c w1[o][c][tap] * y0[m][c] =====
__global__ __launch_bounds__(256) void k5_gemm(const float* __restrict__ w1) {
    __shared__ float Ys[64][33];
    __shared__ float Ws[64][33];
    int m0 = blockIdx.x * 64, n0 = blockIdx.y * 64;
    int tid = threadIdx.x;
    int tn4 = (tid & 15) * 4, tm4 = (tid >> 4) * 4;
    float acc[4][4] = {};
    for (int kc = 0; kc < 4; kc++) {
        int k0 = kc * 32;
        __syncthreads();
        for (int idx = tid; idx < 2048; idx += 256) {
            int row = idx >> 5, col = idx & 31;
            Ys[row][col] = g_y0[(m0 + row)*128 + k0 + col];
            int n = n0 + row;
            int o = n & 127, tap = n >> 7;
            Ws[row][col] = w1[(o*128 + k0 + col)*9 + tap];
        }
        __syncthreads();
        #pragma unroll
        for (int kk = 0; kk < 32; kk++) {
            float a[4], bb[4];
            #pragma unroll
            for (int i = 0; i < 4; i++) a[i] = Ys[tm4+i][kk];
            #pragma unroll
            for (int j = 0; j < 4; j++) bb[j] = Ws[tn4+j][kk];
            #pragma unroll
            for (int i = 0; i < 4; i++)
              #pragma unroll
              for (int j = 0; j < 4; j++)
                acc[i][j] += a[i]*bb[j];
        }
    }
    #pragma unroll
    for (int i = 0; i < 4; i++)
      #pragma unroll
      for (int j = 0; j < 4; j++)
        g_T[(m0 + tm4 + i)*1152 + n0 + tn4 + j] = acc[i][j];
}

// ============ K6: gather + 9-type recombination + relu + dconv2 + store x_hat ===
__global__ __launch_bounds__(128) void k6_dec(const float* __restrict__ b1,
        const float* __restrict__ w2, const float* __restrict__ b2,
        float* __restrict__ out) {
    __shared__ float Ts[25][128];
    __shared__ float vss[9][129];
    __shared__ float xv[27];
    int m = blockIdx.x;
    int b = m >> 6, cell = m & 63, gh = cell >> 3, gw = cell & 7;
    int tid = threadIdx.x;
    const int av[5] = {-1, 0, 0, 0, 1};
    const int dv[5] = {-1,-1, 0, 1, 1};
    #pragma unroll
    for (int p = 0; p < 25; p++) {
        const int iv = p / 5, ih = p % 5;
        int gr = gh + av[iv], gc = gw + av[ih];
        float v = 0.f;
        if (gr >= 0 && gr < 8 && gc >= 0 && gc < 8) {
            long long idx = (long long)(b*64 + gr*8 + gc)*1152
                          + (long long)((dv[iv]+1)*3 + (dv[ih]+1))*128 + tid;
            v = g_T[idx];
        }
        Ts[p][tid] = v;
    }
    __syncthreads();
    float bv = b1[tid];
    const int ivt[3][3] = {{0,2,3},{1,2,3},{1,2,4}};   // [row_type][dy+1] -> plane
    #pragma unroll
    for (int ry = 0; ry < 3; ry++)
      #pragma unroll
      for (int rx = 0; rx < 3; rx++) {
        float s = bv;
        #pragma unroll
        for (int dy = 0; dy < 3; dy++)
          #pragma unroll
          for (int dx = 0; dx < 3; dx++)
            s += Ts[ivt[ry][dy]*5 + ivt[rx][dx]][tid];
        vss[ry*3 + rx][tid] = fmaxf(s, 0.f);
      }
    __syncthreads();
    if (tid < 27) {
        int t = tid / 3, c3 = tid % 3;
        float s = b2[c3];
        #pragma unroll 8
        for (int o = 0; o < 128; o++) s += w2[c3*128 + o] * vss[t][o];
        xv[tid] = s;
    }
    __syncthreads();
    for (int i = tid; i < 768; i += 128) {
        int c3 = i >> 8, rem = i & 255, r = rem >> 4, col = rem & 15;
        int ry = (r == 0) ? 0 : (r == 15) ? 2 : 1;
        int rx = (col == 0) ? 0 : (col == 15) ? 2 : 1;
        long long pos = (long long)(b*3 + c3)*16384 + (gh*16 + r)*128 + gw*16 + col;
        out[pos] = xv[(ry*3 + rx)*3 + c3];
    }
}

// ============ K7: deterministic loss reduction ============
__global__ __launch_bounds__(256) void k7_loss(float* __restrict__ out) {
    __shared__ float red[256];
    int tid = threadIdx.x;
    float s = 0.f;
    for (int j = tid; j < 2048; j += 256) s += g_loss[j];
    red[tid] = s;
    __syncthreads();
    for (int st = 128; st > 0; st >>= 1) {
        if (tid < st) red[tid] += red[tid + st];
        __syncthreads();
    }
    if (tid == 0) out[N_XHAT + N_IDX] = 1.25f * red[0] / 131072.0f;
}

// ============ fallback ============
__global__ void k_probe(float* out) { if (threadIdx.x == 0) out[0] = 0.f; }

// ============ launch ============
extern "C" void kernel_launch(void* const* d_in, const int* in_sizes, int n_in,
                              void* d_out, int out_size) {
    cudaStreamCaptureStatus cst = cudaStreamCaptureStatusNone;
    cudaStreamIsCapturing(0, &cst);
    const bool dbg = (cst == cudaStreamCaptureStatusNone);

#define HX_CK(NAME) do { if (dbg) { \
        cudaError_t e_ = cudaStreamSynchronize(0); \
        cudaError_t l_ = cudaGetLastError(); \
        if (e_ != cudaSuccess || l_ != cudaSuccess) { \
            fprintf(stderr, "HXDBG after %s: sync=%s last=%s\n", NAME, \
                    cudaGetErrorString(e_), cudaGetErrorString(l_)); \
            fflush(stderr); return; } } } while (0)

    static const int sig_ins[14] = {1572864, 3456, 128, 147456, 128, 8192, 64,
                                    32768, 8192, 128, 147456, 128, 384, 3};
    bool is_ins = (n_in >= 14);
    for (int i = 0; i < 14 && is_ins; i++)
        if (in_sizes[i] != sig_ins[i]) is_ins = false;
    if (!is_ins || out_size < N_FULL) {
        k_probe<<<1, 32>>>((float*)d_out);
        HX_CK("probe");
        return;
    }

    const float* x   = (const float*)d_in[0];
    const float* ew1 = (const float*)d_in[1];
    const float* eb1 = (const float*)d_in[2];
    const float* ew2 = (const float*)d_in[3];
    const float* eb2 = (const float*)d_in[4];
    const float* pw  = (const float*)d_in[5];
    const float* pb  = (const float*)d_in[6];
    const float* cb  = (const float*)d_in[7];
    const float* dpw = (const float*)d_in[8];
    const float* dpb = (const float*)d_in[9];
    const float* dw1 = (const float*)d_in[10];
    const float* db1 = (const float*)d_in[11];
    const float* dw2 = (const float*)d_in[12];
    const float* db2 = (const float*)d_in[13];
    float* out = (float*)d_out;

    k1_conv1<<<dim3(4, 4, 32), 256>>>(x, ew1, eb1);
    HX_CK("k1_conv1");
    k2_conv2<<<dim3(2, 8, 32), 256>>>(ew2, eb2);
    HX_CK("k2_conv2");
    k3_fused<<<128, 256>>>(pw, pb, cb, dpw, dpb, out);
    HX_CK("k3_fused");
    k5_gemm<<<dim3(32, 18), 256>>>(dw1);
    HX_CK("k5_gemm");
    k6_dec<<<2048, 128>>>(db1, dw2, db2, out);
    HX_CK("k6_dec");
    k7_loss<<<1, 256>>>(out);
    HX_CK("k7_loss");
#undef HX_CK
}